// round 6
// baseline (speedup 1.0000x reference)
#include <cuda_runtime.h>
#include <math.h>

#define N_NODES 50000
#define N_EDGES 800000
#define DIM 128
#define EPS_BETA 1e-6f
#define EPS_BN 1e-5f

// ---------------- scratch (device globals; no allocation allowed) ----------
__device__ float  d_z[N_NODES * DIM];      // fc output
__device__ float  d_ssrc[N_NODES];         // z . w_src
__device__ float  d_sdst[N_NODES];         // z . w_dst
__device__ float  d_hnew[N_NODES * DIM];   // aggregated output (pre-BN)
__device__ int    d_deg[N_NODES];
__device__ int    d_rowstart[N_NODES + 1];
__device__ int    d_cursor[N_NODES];
__device__ int    d_src_csr[N_EDGES];
__device__ float  d_sigma_csr[N_EDGES];
__device__ double d_colsum[DIM];
__device__ double d_colsq[DIM];
__device__ float  d_scale[DIM];
__device__ float  d_shift[DIM];

// ---------------- init ------------------------------------------------------
__global__ void init_kernel() {
    int i = blockIdx.x * blockDim.x + threadIdx.x;
    int stride = gridDim.x * blockDim.x;
    for (int idx = i; idx < N_NODES; idx += stride) d_deg[idx] = 0;
    if (i < DIM) { d_colsum[i] = 0.0; d_colsq[i] = 0.0; }
}

// ---------------- GEMM: z = h @ fc_w + fc_b, fused attention projections ----
__global__ void gemm_kernel(const float* __restrict__ h,
                            const float* __restrict__ fc_w,
                            const float* __restrict__ fc_b,
                            const float* __restrict__ attn_w) {
    __shared__ float hs[64][DIM];   // 32 KB

    const int base = blockIdx.x * 64;
    const int t  = threadIdx.x;
    const int tx = t & 31;
    const int ty = t >> 5;

    {
        float4* hs4 = reinterpret_cast<float4*>(&hs[0][0]);
        const float4* hg = reinterpret_cast<const float4*>(h + (size_t)base * DIM);
        const int nvec = 64 * DIM / 4;
        const int valid_rows = min(64, N_NODES - base);
        const int valid_vec = valid_rows * DIM / 4;
        for (int i = t; i < nvec; i += 256) {
            float4 v = (i < valid_vec) ? __ldg(hg + i) : make_float4(0.f, 0.f, 0.f, 0.f);
            hs4[i] = v;
        }
    }
    __syncthreads();

    float4 acc[8];
#pragma unroll
    for (int r = 0; r < 8; r++) acc[r] = make_float4(0.f, 0.f, 0.f, 0.f);

#pragma unroll 4
    for (int k = 0; k < DIM; k++) {
        float4 w4 = __ldg(reinterpret_cast<const float4*>(fc_w + (size_t)k * DIM) + tx);
#pragma unroll
        for (int r = 0; r < 8; r++) {
            float hv = hs[ty * 8 + r][k];
            acc[r].x = fmaf(hv, w4.x, acc[r].x);
            acc[r].y = fmaf(hv, w4.y, acc[r].y);
            acc[r].z = fmaf(hv, w4.z, acc[r].z);
            acc[r].w = fmaf(hv, w4.w, acc[r].w);
        }
    }

    float4 b4   = __ldg(reinterpret_cast<const float4*>(fc_b) + tx);
    float4 wsrc = __ldg(reinterpret_cast<const float4*>(attn_w) + tx);
    float4 wdst = __ldg(reinterpret_cast<const float4*>(attn_w + DIM) + tx);

#pragma unroll
    for (int r = 0; r < 8; r++) {
        int row = base + ty * 8 + r;
        if (row >= N_NODES) break;
        float4 zv;
        zv.x = acc[r].x + b4.x;
        zv.y = acc[r].y + b4.y;
        zv.z = acc[r].z + b4.z;
        zv.w = acc[r].w + b4.w;
        reinterpret_cast<float4*>(d_z + (size_t)row * DIM)[tx] = zv;

        float ps = zv.x * wsrc.x + zv.y * wsrc.y + zv.z * wsrc.z + zv.w * wsrc.w;
        float pd = zv.x * wdst.x + zv.y * wdst.y + zv.z * wdst.z + zv.w * wdst.w;
#pragma unroll
        for (int off = 16; off > 0; off >>= 1) {
            ps += __shfl_down_sync(0xFFFFFFFFu, ps, off);
            pd += __shfl_down_sync(0xFFFFFFFFu, pd, off);
        }
        if (tx == 0) { d_ssrc[row] = ps; d_sdst[row] = pd; }
    }
}

// ---------------- CSR build --------------------------------------------------
__global__ void hist_kernel(const int* __restrict__ dst) {
    int i = blockIdx.x * blockDim.x + threadIdx.x;
    if (i >= N_EDGES) return;
    atomicAdd(&d_deg[__ldg(dst + i)], 1);
}

// single-block exclusive scan over 50K degrees (1024 threads x 49 elems each)
__global__ void scan_kernel() {
    __shared__ int sh[1024];
    const int t = threadIdx.x;
    const int per = (N_NODES + 1023) / 1024;       // 49
    const int base = t * per;
    int local = 0;
    for (int k = 0; k < per; k++) {
        int idx = base + k;
        if (idx < N_NODES) local += d_deg[idx];
    }
    sh[t] = local;
    __syncthreads();
    // Hillis-Steele inclusive scan
    for (int off = 1; off < 1024; off <<= 1) {
        int v = (t >= off) ? sh[t - off] : 0;
        __syncthreads();
        sh[t] += v;
        __syncthreads();
    }
    int run = sh[t] - local;                        // exclusive offset
    for (int k = 0; k < per; k++) {
        int idx = base + k;
        if (idx < N_NODES) {
            d_rowstart[idx] = run;
            d_cursor[idx]   = run;
            run += d_deg[idx];
        }
    }
    if (t == 0) d_rowstart[N_NODES] = N_EDGES;
}

__global__ void fill_kernel(const int* __restrict__ src, const int* __restrict__ dst,
                            const float* __restrict__ sigma) {
    int i = blockIdx.x * blockDim.x + threadIdx.x;
    if (i >= N_EDGES) return;
    int d = __ldg(dst + i);
    int pos = atomicAdd(&d_cursor[d], 1);
    d_src_csr[pos]   = __ldg(src + i);
    d_sigma_csr[pos] = __ldg(sigma + i);
}

// ---------------- fused per-node softmax + aggregation ----------------------
// One warp per node. Softmax shift-invariance => skip segment-max.
// h_new[n] = (1/(sum_ex*(sum_sg+eps))) * sum_j exp(e_j)*sigma_j*z[src_j]
__global__ void node_kernel(const float* __restrict__ attn_b) {
    int gid  = blockIdx.x * blockDim.x + threadIdx.x;
    int node = gid >> 5;
    int lane = gid & 31;
    if (node >= N_NODES) return;

    int start = d_rowstart[node];
    int end   = d_rowstart[node + 1];
    float4 acc = make_float4(0.f, 0.f, 0.f, 0.f);
    float4* outp = reinterpret_cast<float4*>(d_hnew + (size_t)node * DIM) + lane;

    if (start == end) { *outp = acc; return; }

    const float sd = d_sdst[node];
    const float b  = __ldg(attn_b);

    // pass A: lane-strided softmax + sigma sums
    float sum_ex = 0.f, sum_sg = 0.f;
    for (int j = start + lane; j < end; j += 32) {
        float a = d_ssrc[d_src_csr[j]] + sd + b;
        float e = (a > 0.f) ? a : 0.01f * a;
        sum_ex += __expf(e);
        sum_sg += d_sigma_csr[j];
    }
#pragma unroll
    for (int off = 16; off > 0; off >>= 1) {
        sum_ex += __shfl_xor_sync(0xFFFFFFFFu, sum_ex, off);
        sum_sg += __shfl_xor_sync(0xFFFFFFFFu, sum_sg, off);
    }
    const float inv = 1.0f / (sum_ex * (sum_sg + EPS_BETA));

    // pass B: serial over edges, all lanes recompute weight (broadcast loads),
    // gather z[src] (float4 per lane) and accumulate in registers
    for (int j = start; j < end; j++) {
        int   s = d_src_csr[j];                     // uniform -> broadcast
        float a = d_ssrc[s] + sd + b;               // uniform -> broadcast
        float e = (a > 0.f) ? a : 0.01f * a;
        float w = __expf(e) * d_sigma_csr[j];
        float4 zv = __ldg(reinterpret_cast<const float4*>(d_z + (size_t)s * DIM) + lane);
        acc.x = fmaf(w, zv.x, acc.x);
        acc.y = fmaf(w, zv.y, acc.y);
        acc.z = fmaf(w, zv.z, acc.z);
        acc.w = fmaf(w, zv.w, acc.w);
    }
    acc.x *= inv; acc.y *= inv; acc.z *= inv; acc.w *= inv;
    *outp = acc;
}

// ---------------- BN column stats -------------------------------------------
__global__ void stats_kernel() {
    int col = threadIdx.x;              // 128 threads
    double s = 0.0, sq = 0.0;
    for (int row = blockIdx.x; row < N_NODES; row += gridDim.x) {
        float v = d_hnew[(size_t)row * DIM + col];
        s  += (double)v;
        sq += (double)v * (double)v;
    }
    atomicAdd(&d_colsum[col], s);
    atomicAdd(&d_colsq[col], sq);
}

__global__ void finalize_kernel(const float* __restrict__ gamma,
                                const float* __restrict__ beta) {
    int c = threadIdx.x;
    if (c >= DIM) return;
    double mu  = d_colsum[c] / (double)N_NODES;
    double var = d_colsq[c] / (double)N_NODES - mu * mu;
    float rstd = rsqrtf((float)var + EPS_BN);
    float g = __ldg(gamma + c);
    float b = __ldg(beta + c);
    d_scale[c] = rstd * g;
    d_shift[c] = b - (float)mu * rstd * g;
}

// ---------------- normalize + ELU -------------------------------------------
__global__ void output_kernel(float* __restrict__ out) {
    int i = blockIdx.x * blockDim.x + threadIdx.x;
    if (i >= N_NODES * DIM) return;
    int c = i & (DIM - 1);
    float x = d_hnew[i] * d_scale[c] + d_shift[c];
    out[i] = (x > 0.f) ? x : expm1f(x);
}

// ---------------- launch -----------------------------------------------------
extern "C" void kernel_launch(void* const* d_in, const int* in_sizes, int n_in,
                              void* d_out, int out_size) {
    const float* h      = (const float*)d_in[0];
    const int*   src    = (const int*)  d_in[1];
    const int*   dst    = (const int*)  d_in[2];
    const float* sigma  = (const float*)d_in[3];
    const float* fc_w   = (const float*)d_in[4];
    const float* fc_b   = (const float*)d_in[5];
    const float* attn_w = (const float*)d_in[6];
    const float* attn_b = (const float*)d_in[7];
    const float* gamma  = (const float*)d_in[8];
    const float* beta   = (const float*)d_in[9];
    float* out = (float*)d_out;

    const int EB = (N_EDGES + 255) / 256;

    init_kernel<<<64, 256>>>();
    gemm_kernel<<<(N_NODES + 63) / 64, 256>>>(h, fc_w, fc_b, attn_w);

    hist_kernel<<<EB, 256>>>(dst);
    scan_kernel<<<1, 1024>>>();
    fill_kernel<<<EB, 256>>>(src, dst, sigma);

    // one warp per node: 8 nodes per 256-thread block
    node_kernel<<<(N_NODES + 7) / 8, 256>>>(attn_b);

    stats_kernel<<<512, 128>>>();
    finalize_kernel<<<1, 128>>>(gamma, beta);
    output_kernel<<<(N_NODES * DIM + 1023) / 1024, 1024>>>(out);
}

// round 8
// speedup vs baseline: 1.3735x; 1.3735x over previous
#include <cuda_runtime.h>
#include <math.h>

#define N_NODES 50000
#define N_EDGES 800000
#define DIM 128
#define EPS_BETA 1e-6f
#define EPS_BN 1e-5f
#define CHUNK 256
#define NCHUNK ((N_NODES + CHUNK - 1) / CHUNK)   // 196

// ---------------- scratch (device globals; no allocation allowed) ----------
__device__ float  d_z[N_NODES * DIM];      // fc output
__device__ float  d_ssrc[N_NODES];         // z . w_src
__device__ float  d_sdst[N_NODES];         // z . w_dst
__device__ float  d_hnew[N_NODES * DIM];   // aggregated output (pre-BN)
__device__ int    d_deg[N_NODES];
__device__ int    d_rowstart[N_NODES + 1];
__device__ int    d_cursor[N_NODES];
__device__ int    d_src_csr[N_EDGES];
__device__ float  d_sigma_csr[N_EDGES];
__device__ int    d_chunksum[NCHUNK];
__device__ int    d_chunkoff[NCHUNK];
__device__ double d_colsum[DIM];
__device__ double d_colsq[DIM];
__device__ float  d_scale[DIM];
__device__ float  d_shift[DIM];

// ---------------- init ------------------------------------------------------
__global__ void init_kernel() {
    int i = blockIdx.x * blockDim.x + threadIdx.x;
    int stride = gridDim.x * blockDim.x;
    for (int idx = i; idx < N_NODES; idx += stride) d_deg[idx] = 0;
    if (i < DIM) { d_colsum[i] = 0.0; d_colsq[i] = 0.0; }
}

// ---------------- GEMM: z = h @ fc_w + fc_b, fused attention projections ----
__global__ void gemm_kernel(const float* __restrict__ h,
                            const float* __restrict__ fc_w,
                            const float* __restrict__ fc_b,
                            const float* __restrict__ attn_w) {
    __shared__ float hs[64][DIM];   // 32 KB

    const int base = blockIdx.x * 64;
    const int t  = threadIdx.x;
    const int tx = t & 31;
    const int ty = t >> 5;

    {
        float4* hs4 = reinterpret_cast<float4*>(&hs[0][0]);
        const float4* hg = reinterpret_cast<const float4*>(h + (size_t)base * DIM);
        const int nvec = 64 * DIM / 4;
        const int valid_rows = min(64, N_NODES - base);
        const int valid_vec = valid_rows * DIM / 4;
        for (int i = t; i < nvec; i += 256) {
            float4 v = (i < valid_vec) ? __ldg(hg + i) : make_float4(0.f, 0.f, 0.f, 0.f);
            hs4[i] = v;
        }
    }
    __syncthreads();

    float4 acc[8];
#pragma unroll
    for (int r = 0; r < 8; r++) acc[r] = make_float4(0.f, 0.f, 0.f, 0.f);

#pragma unroll 4
    for (int k = 0; k < DIM; k++) {
        float4 w4 = __ldg(reinterpret_cast<const float4*>(fc_w + (size_t)k * DIM) + tx);
#pragma unroll
        for (int r = 0; r < 8; r++) {
            float hv = hs[ty * 8 + r][k];
            acc[r].x = fmaf(hv, w4.x, acc[r].x);
            acc[r].y = fmaf(hv, w4.y, acc[r].y);
            acc[r].z = fmaf(hv, w4.z, acc[r].z);
            acc[r].w = fmaf(hv, w4.w, acc[r].w);
        }
    }

    float4 b4   = __ldg(reinterpret_cast<const float4*>(fc_b) + tx);
    float4 wsrc = __ldg(reinterpret_cast<const float4*>(attn_w) + tx);
    float4 wdst = __ldg(reinterpret_cast<const float4*>(attn_w + DIM) + tx);

#pragma unroll
    for (int r = 0; r < 8; r++) {
        int row = base + ty * 8 + r;
        if (row >= N_NODES) break;
        float4 zv;
        zv.x = acc[r].x + b4.x;
        zv.y = acc[r].y + b4.y;
        zv.z = acc[r].z + b4.z;
        zv.w = acc[r].w + b4.w;
        reinterpret_cast<float4*>(d_z + (size_t)row * DIM)[tx] = zv;

        float ps = zv.x * wsrc.x + zv.y * wsrc.y + zv.z * wsrc.z + zv.w * wsrc.w;
        float pd = zv.x * wdst.x + zv.y * wdst.y + zv.z * wdst.z + zv.w * wdst.w;
#pragma unroll
        for (int off = 16; off > 0; off >>= 1) {
            ps += __shfl_down_sync(0xFFFFFFFFu, ps, off);
            pd += __shfl_down_sync(0xFFFFFFFFu, pd, off);
        }
        if (tx == 0) { d_ssrc[row] = ps; d_sdst[row] = pd; }
    }
}

// ---------------- CSR build --------------------------------------------------
__global__ void hist_kernel(const int* __restrict__ dst) {
    int i = blockIdx.x * blockDim.x + threadIdx.x;
    if (i >= N_EDGES) return;
    atomicAdd(&d_deg[__ldg(dst + i)], 1);
}

// level 1: per-chunk sums (grid = NCHUNK, block = 256)
__global__ void chunksum_kernel() {
    __shared__ int sh[8];
    int idx = blockIdx.x * CHUNK + threadIdx.x;
    int v = (idx < N_NODES) ? d_deg[idx] : 0;
#pragma unroll
    for (int off = 16; off > 0; off >>= 1) v += __shfl_xor_sync(0xFFFFFFFFu, v, off);
    if ((threadIdx.x & 31) == 0) sh[threadIdx.x >> 5] = v;
    __syncthreads();
    if (threadIdx.x < 8) {
        int s = sh[threadIdx.x];
#pragma unroll
        for (int off = 4; off > 0; off >>= 1) s += __shfl_xor_sync(0xFFu, s, off);
        if (threadIdx.x == 0) d_chunksum[blockIdx.x] = s;
    }
}

// level 2: exclusive scan of NCHUNK (=196) chunk sums in ONE small block
__global__ void chunkscan_kernel() {
    __shared__ int sh[256];
    int t = threadIdx.x;
    int v = (t < NCHUNK) ? d_chunksum[t] : 0;
    sh[t] = v;
    __syncthreads();
#pragma unroll
    for (int off = 1; off < 256; off <<= 1) {
        int u = (t >= off) ? sh[t - off] : 0;
        __syncthreads();
        sh[t] += u;
        __syncthreads();
    }
    if (t < NCHUNK) d_chunkoff[t] = sh[t] - v;     // exclusive
    if (t == 0) d_rowstart[N_NODES] = N_EDGES;
}

// level 3: in-block exclusive scan of degrees + chunk offset -> rowstart
__global__ void rowstart_kernel() {
    __shared__ int sh[256];
    __shared__ int warp_sums[8];
    int t = threadIdx.x;
    int idx = blockIdx.x * CHUNK + t;
    int v = (idx < N_NODES) ? d_deg[idx] : 0;

    // warp inclusive scan
    int incl = v;
#pragma unroll
    for (int off = 1; off < 32; off <<= 1) {
        int u = __shfl_up_sync(0xFFFFFFFFu, incl, off);
        if ((t & 31) >= off) incl += u;
    }
    if ((t & 31) == 31) warp_sums[t >> 5] = incl;
    __syncthreads();
    if (t < 8) {
        int s = warp_sums[t];
        int si = s;
#pragma unroll
        for (int off = 1; off < 8; off <<= 1) {
            int u = __shfl_up_sync(0xFFu, si, off);
            if (t >= off) si += u;
        }
        warp_sums[t] = si - s;                      // exclusive warp offsets
    }
    __syncthreads();
    int excl = incl - v + warp_sums[t >> 5];
    if (idx < N_NODES) {
        int rs = d_chunkoff[blockIdx.x] + excl;
        d_rowstart[idx] = rs;
        d_cursor[idx]   = rs;
    }
    (void)sh;
}

__global__ void fill_kernel(const int* __restrict__ src, const int* __restrict__ dst,
                            const float* __restrict__ sigma) {
    int i = blockIdx.x * blockDim.x + threadIdx.x;
    if (i >= N_EDGES) return;
    int d = __ldg(dst + i);
    int pos = atomicAdd(&d_cursor[d], 1);
    d_src_csr[pos]   = __ldg(src + i);
    d_sigma_csr[pos] = __ldg(sigma + i);
}

// ---------------- fused per-node softmax + aggregation ----------------------
// One warp per node. Softmax shift-invariance => skip segment-max.
// h_new[n] = (1/(sum_ex*(sum_sg+eps))) * sum_j exp(e_j)*sigma_j*z[src_j]
__global__ void node_kernel(const float* __restrict__ attn_b) {
    int gid  = blockIdx.x * blockDim.x + threadIdx.x;
    int node = gid >> 5;
    int lane = gid & 31;
    if (node >= N_NODES) return;

    int start = d_rowstart[node];
    int end   = d_rowstart[node + 1];
    float4 acc = make_float4(0.f, 0.f, 0.f, 0.f);
    float4* outp = reinterpret_cast<float4*>(d_hnew + (size_t)node * DIM) + lane;

    if (start == end) { *outp = acc; return; }

    const float sd = d_sdst[node];
    const float b  = __ldg(attn_b);

    // pass A: lane-strided softmax + sigma sums
    float sum_ex = 0.f, sum_sg = 0.f;
    for (int j = start + lane; j < end; j += 32) {
        float a = d_ssrc[d_src_csr[j]] + sd + b;
        float e = (a > 0.f) ? a : 0.01f * a;
        sum_ex += __expf(e);
        sum_sg += d_sigma_csr[j];
    }
#pragma unroll
    for (int off = 16; off > 0; off >>= 1) {
        sum_ex += __shfl_xor_sync(0xFFFFFFFFu, sum_ex, off);
        sum_sg += __shfl_xor_sync(0xFFFFFFFFu, sum_sg, off);
    }
    const float inv = 1.0f / (sum_ex * (sum_sg + EPS_BETA));

    // pass B: serial over edges, all lanes recompute weight (broadcast loads),
    // gather z[src] (float4 per lane) and accumulate in registers
    for (int j = start; j < end; j++) {
        int   s = d_src_csr[j];                     // uniform -> broadcast
        float a = d_ssrc[s] + sd + b;               // uniform -> broadcast
        float e = (a > 0.f) ? a : 0.01f * a;
        float w = __expf(e) * d_sigma_csr[j];
        float4 zv = __ldg(reinterpret_cast<const float4*>(d_z + (size_t)s * DIM) + lane);
        acc.x = fmaf(w, zv.x, acc.x);
        acc.y = fmaf(w, zv.y, acc.y);
        acc.z = fmaf(w, zv.z, acc.z);
        acc.w = fmaf(w, zv.w, acc.w);
    }
    acc.x *= inv; acc.y *= inv; acc.z *= inv; acc.w *= inv;
    *outp = acc;
}

// ---------------- BN column stats -------------------------------------------
__global__ void stats_kernel() {
    int col = threadIdx.x;              // 128 threads
    double s = 0.0, sq = 0.0;
    for (int row = blockIdx.x; row < N_NODES; row += gridDim.x) {
        float v = d_hnew[(size_t)row * DIM + col];
        s  += (double)v;
        sq += (double)v * (double)v;
    }
    atomicAdd(&d_colsum[col], s);
    atomicAdd(&d_colsq[col], sq);
}

__global__ void finalize_kernel(const float* __restrict__ gamma,
                                const float* __restrict__ beta) {
    int c = threadIdx.x;
    if (c >= DIM) return;
    double mu  = d_colsum[c] / (double)N_NODES;
    double var = d_colsq[c] / (double)N_NODES - mu * mu;
    float rstd = rsqrtf((float)var + EPS_BN);
    float g = __ldg(gamma + c);
    float b = __ldg(beta + c);
    d_scale[c] = rstd * g;
    d_shift[c] = b - (float)mu * rstd * g;
}

// ---------------- normalize + ELU -------------------------------------------
__global__ void output_kernel(float* __restrict__ out) {
    int i = blockIdx.x * blockDim.x + threadIdx.x;
    if (i >= N_NODES * DIM) return;
    int c = i & (DIM - 1);
    float x = d_hnew[i] * d_scale[c] + d_shift[c];
    out[i] = (x > 0.f) ? x : expm1f(x);
}

// ---------------- launch -----------------------------------------------------
extern "C" void kernel_launch(void* const* d_in, const int* in_sizes, int n_in,
                              void* d_out, int out_size) {
    const float* h      = (const float*)d_in[0];
    const int*   src    = (const int*)  d_in[1];
    const int*   dst    = (const int*)  d_in[2];
    const float* sigma  = (const float*)d_in[3];
    const float* fc_w   = (const float*)d_in[4];
    const float* fc_b   = (const float*)d_in[5];
    const float* attn_w = (const float*)d_in[6];
    const float* attn_b = (const float*)d_in[7];
    const float* gamma  = (const float*)d_in[8];
    const float* beta   = (const float*)d_in[9];
    float* out = (float*)d_out;

    const int EB = (N_EDGES + 255) / 256;

    init_kernel<<<64, 256>>>();
    gemm_kernel<<<(N_NODES + 63) / 64, 256>>>(h, fc_w, fc_b, attn_w);

    hist_kernel<<<EB, 256>>>(dst);
    chunksum_kernel<<<NCHUNK, 256>>>();
    chunkscan_kernel<<<1, 256>>>();
    rowstart_kernel<<<NCHUNK, 256>>>();
    fill_kernel<<<EB, 256>>>(src, dst, sigma);

    // one warp per node: 8 nodes per 256-thread block
    node_kernel<<<(N_NODES + 7) / 8, 256>>>(attn_b);

    stats_kernel<<<512, 128>>>();
    finalize_kernel<<<1, 128>>>(gamma, beta);
    output_kernel<<<(N_NODES * DIM + 1023) / 1024, 1024>>>(out);
}